// round 13
// baseline (speedup 1.0000x reference)
#include <cuda_runtime.h>
#include <cstdint>

#define NHITS 80000
#define KOBJ  512
#define NREP  32
#define KCHUNK 64
#define NCHUNK (KOBJ / KCHUNK)     // 8
#define EPSF  1e-9f

#define NBX1 157                    // ceil(80000/512), 2 hits per thread
#define NBX3 157                    // ceil(80000/512), 2 hits per thread
#define TOTAL_P3_BLOCKS (NBX3 * NCHUNK)          // 1256
#define SCRATCH_TOT (NREP * KOBJ)                // 16384
#define ZERO_PER_BLOCK ((SCRATCH_TOT + TOTAL_P3_BLOCKS - 1) / TOTAL_P3_BLOCKS) // 14

// ---------------- device scratch (zero at load; re-zeroed by phase3 each run)
__device__ unsigned long long g_packed[NREP][KOBJ];
__device__ int    g_cnt[NREP][KOBJ];
__device__ float  g_num[NREP][KOBJ];
__device__ float  g_den[NREP][KOBJ];
__device__ float  g_q[NHITS];
__device__ float4 g_obj[KOBJ];      // (m2ox, m2oy, ozeps, rep_w)
__device__ float  g_attw[KOBJ];
__device__ float  g_wsum[NCHUNK];   // per-chunk sum of repulsion weights
__device__ float  g_scal[8];        // 0:noise_b 1:noise_cnt 2:cc 3:pot 4:beta+pay 6:nobj
__device__ unsigned g_ticket1;
__device__ unsigned g_ticket3;

// ---------------- helpers ----------------
__device__ __forceinline__ float softclipf(float x, float s) {
    float y = x / s;
    y = (y > 1.0f) ? __logf(y + 1.0f) : y;
    return y * s;
}
__device__ __forceinline__ float huberf(float x, float d) {
    float ax = fabsf(x);
    return (ax < d) ? x * x : d * d + 2.0f * d * (ax - d);
}
__device__ __forceinline__ float warpSum(float v) {
    #pragma unroll
    for (int o = 16; o > 0; o >>= 1) v += __shfl_down_sync(0xffffffffu, v, o);
    return v;
}
__device__ __forceinline__ float sqrt_approx(float x) {
    float r;
    asm("sqrt.approx.f32 %0, %1;" : "=f"(r) : "f"(x));
    return r;
}
__device__ __forceinline__ float fast_atanh(float b) {
    return 0.5f * __logf(__fdividef(1.0f + b, 1.0f - b));
}

// per-hit payload path (object hits only)
__device__ __forceinline__ void hit_obj(
    int n, int rep, int t, float b,
    float te, float pe, float tt_, float pt_,
    float2 tp, float2 pp, float cls)
{
    atomicAdd(&g_cnt[rep][t], 1);
    unsigned long long pk =
        ((unsigned long long)__float_as_uint(b) << 32) |
        (unsigned long long)(0xFFFFFFFFu - (unsigned)n);
    atomicMax(&g_packed[rep][t], pk);
    float ed = fabsf(te - pe);
    float le = 10.0f * __expf(-0.1f * ed * ed) + 0.01f * ed;
    le = softclipf(le, 10.0f);
    float dpx = tp.x - pp.x, dpy = tp.y - pp.y;
    float d2p = fmaf(dpx, dpx, dpy * dpy);
    float pl = softclipf(huberf(sqrt_approx(fmaf(d2p, 0.01f, 0.01f)), 10.0f), 3.0f);
    float tl = softclipf(huberf(tt_ - pt_, 2.0f), 6.0f);
    float payload = le + pl + tl + cls;
    float ew = (te > 10.0f) ? 1.0f : fmaxf((te - 0.5f) * (1.0f / 9.5f), 0.0f);
    float pw = b * ew;
    atomicAdd(&g_num[rep][t], payload * pw);
    atomicAdd(&g_den[rep][t], pw);
}

// ---------------- phase 1: per-hit pass (2 hits/thread) + fused phase 2 ----
__global__ void __launch_bounds__(256) k_phase1(
    const float2* __restrict__ pb2, const float4* __restrict__ cc4,
    const float2* __restrict__ pE2, const float4* __restrict__ pPos4,
    const float2* __restrict__ pT2, const float4* __restrict__ pId4,
    const int2*   __restrict__ tIdx2, const float2* __restrict__ tE2,
    const float4* __restrict__ tPos4, const float2* __restrict__ tT2,
    const float2* __restrict__ cc)
{
    int m = blockIdx.x * 256 + threadIdx.x;      // pair index: hits 2m, 2m+1
    int rep = ((blockIdx.x << 1) | (threadIdx.x >> 7)) & (NREP - 1);
    float nb = 0.0f, ncnt = 0.0f, ccs = 0.0f;
    if (2 * m < NHITS) {
        float2 bb = pb2[m];
        float4 cv = cc4[m];
        int2   tv = tIdx2[m];
        float2 te = tE2[m];
        float2 pe = pE2[m];
        float4 tp = tPos4[m];
        float4 pp = pPos4[m];
        float2 tt_ = tT2[m];
        float2 pt_ = pT2[m];
        float4 i0 = pId4[3 * m], i1 = pId4[3 * m + 1], i2 = pId4[3 * m + 2];

        ccs = fmaf(cv.x, cv.x, cv.y * cv.y) + fmaf(cv.z, cv.z, cv.w * cv.w);

        {
            float b = fminf(fmaxf(bb.x, 1e-6f), 1.0f - 1e-6f);
            float at = fast_atanh(b);
            g_q[2 * m] = fmaf(at, at, 0.1f);
            float cls = (i0.x * i0.x + i0.y * i0.y + i0.z * i0.z
                       + i0.w * i0.w + i1.x * i1.x + i1.y * i1.y) * (1e-8f / 6.0f);
            if (tv.x >= 0) {
                hit_obj(2 * m, rep, tv.x, b, te.x, pe.x, tt_.x, pt_.x,
                        make_float2(tp.x, tp.y), make_float2(pp.x, pp.y), cls);
            } else { nb += b; ncnt += 1.0f; }
        }
        {
            float b = fminf(fmaxf(bb.y, 1e-6f), 1.0f - 1e-6f);
            float at = fast_atanh(b);
            g_q[2 * m + 1] = fmaf(at, at, 0.1f);
            float cls = (i1.z * i1.z + i1.w * i1.w + i2.x * i2.x
                       + i2.y * i2.y + i2.z * i2.z + i2.w * i2.w) * (1e-8f / 6.0f);
            if (tv.y >= 0) {
                hit_obj(2 * m + 1, rep, tv.y, b, te.y, pe.y, tt_.y, pt_.y,
                        make_float2(tp.z, tp.w), make_float2(pp.z, pp.w), cls);
            } else { nb += b; ncnt += 1.0f; }
        }
    }
    __shared__ float sr[3][8];
    float w0 = warpSum(nb), w1 = warpSum(ncnt), w2 = warpSum(ccs);
    int lane = threadIdx.x & 31, wid = threadIdx.x >> 5;
    if (lane == 0) { sr[0][wid] = w0; sr[1][wid] = w1; sr[2][wid] = w2; }
    __syncthreads();
    if (wid == 0) {
        float v0 = (lane < 8) ? sr[0][lane] : 0.0f;
        float v1 = (lane < 8) ? sr[1][lane] : 0.0f;
        float v2 = (lane < 8) ? sr[2][lane] : 0.0f;
        v0 = warpSum(v0); v1 = warpSum(v1); v2 = warpSum(v2);
        if (lane == 0) {
            if (v1 != 0.0f || v0 != 0.0f) {
                atomicAdd(&g_scal[0], v0);
                atomicAdd(&g_scal[1], v1);
            }
            atomicAdd(&g_scal[2], v2);
        }
    }

    // ---- fused phase 2: last block reduces replicas & builds object data ----
    __shared__ bool lastB;
    if (threadIdx.x == 0) {
        __threadfence();
        unsigned tk = atomicAdd(&g_ticket1, 1u);
        lastB = (tk == (unsigned)(NBX1 - 1));
        if (lastB) g_ticket1 = 0;
    }
    __syncthreads();
    if (!lastB) return;
    __threadfence();

    int t = threadIdx.x;           // 0..255, objects 2t, 2t+1
    int k0 = 2 * t;
    int c0 = 0, c1 = 0;
    float n0 = 0.0f, n1 = 0.0f, d0 = 0.0f, d1 = 0.0f;
    unsigned long long p0 = 0ull, p1 = 0ull;
    #pragma unroll
    for (int r = 0; r < NREP; r++) {
        int2 cvv = *(const int2*)&g_cnt[r][k0];
        float2 nv = *(const float2*)&g_num[r][k0];
        float2 dv = *(const float2*)&g_den[r][k0];
        ulonglong2 pv = *(const ulonglong2*)&g_packed[r][k0];
        c0 += cvv.x; c1 += cvv.y;
        n0 += nv.x; n1 += nv.y;
        d0 += dv.x; d1 += dv.y;
        p0 = (pv.x > p0) ? pv.x : p0;
        p1 = (pv.y > p1) ? pv.y : p1;
    }
    float part = 0.0f, nob = 0.0f, wsum = 0.0f;
    float4 O0 = make_float4(0.0f, 0.0f, 1e6f, 0.0f);
    float4 O1 = make_float4(0.0f, 0.0f, 1e6f, 0.0f);
    float aw0 = 0.0f, aw1 = 0.0f;
    if (c0 > 0) {
        float betaA = __uint_as_float((unsigned)(p0 >> 32));
        unsigned alpha = 0xFFFFFFFFu - (unsigned)(p0 & 0xFFFFFFFFull);
        float2 c = cc[alpha];
        float at = fast_atanh(betaA);
        float qa = fmaf(at, at, 0.1f);
        O0.x = -2.0f * c.x;  O0.y = -2.0f * c.y;
        O0.z = fmaf(c.x, c.x, c.y * c.y) + 1e-6f;
        O0.w = qa / ((float)NHITS - (float)c0 + EPSF);
        aw0 = qa / ((float)c0 + EPSF);
        part += (1.0f - betaA) + n0 / (d0 + EPSF);
        nob += 1.0f; wsum += O0.w;
    }
    if (c1 > 0) {
        float betaA = __uint_as_float((unsigned)(p1 >> 32));
        unsigned alpha = 0xFFFFFFFFu - (unsigned)(p1 & 0xFFFFFFFFull);
        float2 c = cc[alpha];
        float at = fast_atanh(betaA);
        float qa = fmaf(at, at, 0.1f);
        O1.x = -2.0f * c.x;  O1.y = -2.0f * c.y;
        O1.z = fmaf(c.x, c.x, c.y * c.y) + 1e-6f;
        O1.w = qa / ((float)NHITS - (float)c1 + EPSF);
        aw1 = qa / ((float)c1 + EPSF);
        part += (1.0f - betaA) + n1 / (d1 + EPSF);
        nob += 1.0f; wsum += O1.w;
    }
    g_obj[k0]     = O0;
    g_obj[k0 + 1] = O1;
    g_attw[k0] = aw0;
    g_attw[k0 + 1] = aw1;
    // objects 2t,2t+1 -> chunk (2t)>>6 = t>>5 (warp-uniform)
    float ws = warpSum(wsum);
    float wp = warpSum(part);
    float wn = warpSum(nob);
    if ((threadIdx.x & 31) == 0) {
        atomicAdd(&g_wsum[threadIdx.x >> 5], ws);
        atomicAdd(&g_scal[4], wp);
        atomicAdd(&g_scal[6], wn);
    }
}

// ---------------- phase 3: 2 hits/thread, scalar, AoS objects, PDL ---------
__global__ void __launch_bounds__(256, 8) k_phase3(
    const float4* __restrict__ cc4, const int2* __restrict__ tIdx2,
    float* __restrict__ out)
{
    // ---- pre-sync prologue: pure-input loads only ----
    int m = blockIdx.x * blockDim.x + threadIdx.x;   // hits 2m, 2m+1
    bool active = (2 * m < NHITS);
    int mc = active ? m : 0;
    float4 cv = cc4[mc];                    // (x0,y0,x1,y1)
    int2   tv = tIdx2[mc];
    float x0 = cv.x, y0 = cv.y, x1 = cv.z, y1 = cv.w;
    float h0 = fmaf(x0, x0, y0 * y0);
    float h1 = fmaf(x1, x1, y1 * y1);

    // wait for phase1 (producer of g_obj/g_q/g_wsum/g_attw; reader of scratch)
    cudaGridDependencySynchronize();

    __shared__ float4 sobj[KCHUNK];
    const int kbase = blockIdx.y * KCHUNK;
    if (threadIdx.x < KCHUNK) sobj[threadIdx.x] = g_obj[kbase + threadIdx.x];
    // distributed re-zero of the replicated scratch
    {
        int lin = blockIdx.y * NBX3 + blockIdx.x;
        if (threadIdx.x < ZERO_PER_BLOCK) {
            int idx = lin * ZERO_PER_BLOCK + threadIdx.x;
            if (idx < SCRATCH_TOT) {
                ((int*)g_cnt)[idx] = 0;
                ((float*)g_num)[idx] = 0.0f;
                ((float*)g_den)[idx] = 0.0f;
                ((unsigned long long*)g_packed)[idx] = 0ull;
            }
        }
    }
    float2 qv = *(const float2*)&g_q[2 * mc];
    __syncthreads();

    float res = 0.0f;
    if (active) {
        float a00 = 0.0f, a01 = 0.0f, a10 = 0.0f, a11 = 0.0f;
        #pragma unroll 4
        for (int k = 0; k < KCHUNK; k += 2) {
            {
                float4 o = sobj[k];
                float t0 = fmaf(o.x, x0, o.z); t0 = fmaf(o.y, y0, t0);
                float t1 = fmaf(o.x, x1, o.z); t1 = fmaf(o.y, y1, t1);
                float d20 = fminf(h0 + t0, 1.0f);
                float d21 = fminf(h1 + t1, 1.0f);
                a00 = fmaf(o.w, sqrt_approx(d20), a00);
                a10 = fmaf(o.w, sqrt_approx(d21), a10);
            }
            {
                float4 o = sobj[k + 1];
                float t0 = fmaf(o.x, x0, o.z); t0 = fmaf(o.y, y0, t0);
                float t1 = fmaf(o.x, x1, o.z); t1 = fmaf(o.y, y1, t1);
                float d20 = fminf(h0 + t0, 1.0f);
                float d21 = fminf(h1 + t1, 1.0f);
                a01 = fmaf(o.w, sqrt_approx(d20), a01);
                a11 = fmaf(o.w, sqrt_approx(d21), a11);
            }
        }
        float W = g_wsum[blockIdx.y];
        res = (W - (a00 + a01)) * qv.x + (W - (a10 + a11)) * qv.y;
        // own-object corrections
        #pragma unroll
        for (int i = 0; i < 2; i++) {
            int t = (i == 0) ? tv.x : tv.y;
            if (t >= kbase && t < kbase + KCHUNK) {
                float x = (i == 0) ? x0 : x1;
                float y = (i == 0) ? y0 : y1;
                float qq = (i == 0) ? qv.x : qv.y;
                float4 o = sobj[t - kbase];
                float dx = fmaf(0.5f, o.x, x);
                float dy = fmaf(0.5f, o.y, y);
                float d2n = fmaf(dx, dx, dy * dy);
                float d = sqrt_approx(d2n + 1e-6f);
                res -= fmaxf(1.0f - d, 0.0f) * o.w * qq;
                res = fmaf(d2n * g_attw[t], qq, res);
            }
        }
    }
    __shared__ float sr[8];
    float wv = warpSum(res);
    int lane = threadIdx.x & 31, wid = threadIdx.x >> 5;
    if (lane == 0) sr[wid] = wv;
    __syncthreads();
    __shared__ bool isLast;
    if (threadIdx.x == 0) isLast = false;
    if (wid == 0) {
        float v = (lane < 8) ? sr[lane] : 0.0f;
        v = warpSum(v);
        if (lane == 0) {
            atomicAdd(&g_scal[3], v);
            __threadfence();
            unsigned tk = atomicAdd(&g_ticket3, 1u);
            isLast = (tk == (unsigned)(TOTAL_P3_BLOCKS - 1));
        }
    }
    __syncthreads();
    if (isLast) {
        if (threadIdx.x == 0) {
            float inv = 1.0f / (g_scal[6] + EPSF);
            float total = (g_scal[3] + g_scal[4]) * inv
                        + g_scal[0] / (g_scal[1] + EPSF)
                        + 0.001f * g_scal[2] * (1.0f / ((float)NHITS * 2.0f));
            out[0] = total;
            g_ticket3 = 0;
        }
        __syncthreads();
        if (threadIdx.x < 8) {
            g_scal[threadIdx.x] = 0.0f;
            g_wsum[threadIdx.x] = 0.0f;
        }
    }
}

// ---------------- launch ----------------
extern "C" void kernel_launch(void* const* d_in, const int* in_sizes, int n_in,
                              void* d_out, int out_size)
{
    const float2* pb2   = (const float2*)d_in[0];
    const float4* cc4   = (const float4*)d_in[1];
    const float2* cc2   = (const float2*)d_in[1];
    const float2* pE2   = (const float2*)d_in[2];
    const float4* pPos4 = (const float4*)d_in[3];
    const float2* pT2   = (const float2*)d_in[4];
    const float4* pId4  = (const float4*)d_in[5];
    const int2*   tIdx2 = (const int2*)  d_in[6];
    const float2* tE2   = (const float2*)d_in[7];
    const float4* tPos4 = (const float4*)d_in[8];
    const float2* tT2   = (const float2*)d_in[9];
    float* out = (float*)d_out;

    k_phase1<<<NBX1, 256>>>(pb2, cc4, pE2, pPos4, pT2, pId4, tIdx2, tE2, tPos4, tT2, cc2);

    cudaLaunchConfig_t cfg = {};
    cfg.gridDim = dim3(NBX3, NCHUNK);
    cfg.blockDim = dim3(256);
    cudaLaunchAttribute attr[1];
    attr[0].id = cudaLaunchAttributeProgrammaticStreamSerialization;
    attr[0].val.programmaticStreamSerializationAllowed = 1;
    cfg.attrs = attr;
    cfg.numAttrs = 1;
    cudaLaunchKernelEx(&cfg, k_phase3, cc4, tIdx2, out);
}

// round 14
// speedup vs baseline: 1.1260x; 1.1260x over previous
#include <cuda_runtime.h>
#include <cstdint>

#define NHITS 80000
#define KOBJ  512
#define NREP  32
#define KCHUNK 64
#define NCHUNK (KOBJ / KCHUNK)     // 8
#define EPSF  1e-9f

#define NBX1 157                    // ceil(80000/512), 2 hits per thread
#define NBX3 157                    // ceil(80000/512), 2 hits per thread
#define TOTAL_P3_BLOCKS (NBX3 * NCHUNK)          // 1256
#define SCRATCH_TOT (NREP * KOBJ)                // 16384
#define ZERO_PER_BLOCK ((SCRATCH_TOT + TOTAL_P3_BLOCKS - 1) / TOTAL_P3_BLOCKS) // 14

// ---------------- device scratch (zero at load; re-zeroed by phase3 each run)
__device__ unsigned long long g_packed[NREP][KOBJ];
__device__ int    g_cnt[NREP][KOBJ];
__device__ float  g_num[NREP][KOBJ];
__device__ float  g_den[NREP][KOBJ];
__device__ float  g_q[NHITS];
__device__ float4 g_obj[KOBJ];      // (m2ox, m2oy, ozeps, rep_w)
__device__ float  g_attw[KOBJ];
__device__ float  g_wsum[NCHUNK];   // per-chunk sum of repulsion weights
__device__ float  g_scal[8];        // 0:noise_b 1:noise_cnt 2:cc 3:pot 4:beta+pay 6:nobj
__device__ unsigned g_ticket1;
__device__ unsigned g_ticket3;

// ---------------- helpers ----------------
__device__ __forceinline__ float softclipf(float x, float s) {
    float y = x / s;
    y = (y > 1.0f) ? __logf(y + 1.0f) : y;
    return y * s;
}
__device__ __forceinline__ float huberf(float x, float d) {
    float ax = fabsf(x);
    return (ax < d) ? x * x : d * d + 2.0f * d * (ax - d);
}
__device__ __forceinline__ float warpSum(float v) {
    #pragma unroll
    for (int o = 16; o > 0; o >>= 1) v += __shfl_down_sync(0xffffffffu, v, o);
    return v;
}
__device__ __forceinline__ float sqrt_approx(float x) {
    float r;
    asm("sqrt.approx.f32 %0, %1;" : "=f"(r) : "f"(x));
    return r;
}
__device__ __forceinline__ float fast_atanh(float b) {
    return 0.5f * __logf(__fdividef(1.0f + b, 1.0f - b));
}

// per-hit payload path (object hits only)
__device__ __forceinline__ void hit_obj(
    int n, int rep, int t, float b,
    float te, float pe, float tt_, float pt_,
    float2 tp, float2 pp, float cls)
{
    atomicAdd(&g_cnt[rep][t], 1);
    unsigned long long pk =
        ((unsigned long long)__float_as_uint(b) << 32) |
        (unsigned long long)(0xFFFFFFFFu - (unsigned)n);
    atomicMax(&g_packed[rep][t], pk);
    float ed = fabsf(te - pe);
    float le = 10.0f * __expf(-0.1f * ed * ed) + 0.01f * ed;
    le = softclipf(le, 10.0f);
    float dpx = tp.x - pp.x, dpy = tp.y - pp.y;
    float d2p = fmaf(dpx, dpx, dpy * dpy);
    float pl = softclipf(huberf(sqrt_approx(fmaf(d2p, 0.01f, 0.01f)), 10.0f), 3.0f);
    float tl = softclipf(huberf(tt_ - pt_, 2.0f), 6.0f);
    float payload = le + pl + tl + cls;
    float ew = (te > 10.0f) ? 1.0f : fmaxf((te - 0.5f) * (1.0f / 9.5f), 0.0f);
    float pw = b * ew;
    atomicAdd(&g_num[rep][t], payload * pw);
    atomicAdd(&g_den[rep][t], pw);
}

// ---------------- phase 1: per-hit pass (2 hits/thread) + fused phase 2 ----
__global__ void __launch_bounds__(256) k_phase1(
    const float2* __restrict__ pb2, const float4* __restrict__ cc4,
    const float2* __restrict__ pE2, const float4* __restrict__ pPos4,
    const float2* __restrict__ pT2, const float4* __restrict__ pId4,
    const int2*   __restrict__ tIdx2, const float2* __restrict__ tE2,
    const float4* __restrict__ tPos4, const float2* __restrict__ tT2,
    const float2* __restrict__ cc)
{
    int m = blockIdx.x * 256 + threadIdx.x;      // pair index: hits 2m, 2m+1
    int rep = ((blockIdx.x << 1) | (threadIdx.x >> 7)) & (NREP - 1);
    float nb = 0.0f, ncnt = 0.0f, ccs = 0.0f;
    if (2 * m < NHITS) {
        float2 bb = pb2[m];
        float4 cv = cc4[m];
        int2   tv = tIdx2[m];
        float2 te = tE2[m];
        float2 pe = pE2[m];
        float4 tp = tPos4[m];
        float4 pp = pPos4[m];
        float2 tt_ = tT2[m];
        float2 pt_ = pT2[m];
        float4 i0 = pId4[3 * m], i1 = pId4[3 * m + 1], i2 = pId4[3 * m + 2];

        ccs = fmaf(cv.x, cv.x, cv.y * cv.y) + fmaf(cv.z, cv.z, cv.w * cv.w);

        {
            float b = fminf(fmaxf(bb.x, 1e-6f), 1.0f - 1e-6f);
            float at = fast_atanh(b);
            g_q[2 * m] = fmaf(at, at, 0.1f);
            float cls = (i0.x * i0.x + i0.y * i0.y + i0.z * i0.z
                       + i0.w * i0.w + i1.x * i1.x + i1.y * i1.y) * (1e-8f / 6.0f);
            if (tv.x >= 0) {
                hit_obj(2 * m, rep, tv.x, b, te.x, pe.x, tt_.x, pt_.x,
                        make_float2(tp.x, tp.y), make_float2(pp.x, pp.y), cls);
            } else { nb += b; ncnt += 1.0f; }
        }
        {
            float b = fminf(fmaxf(bb.y, 1e-6f), 1.0f - 1e-6f);
            float at = fast_atanh(b);
            g_q[2 * m + 1] = fmaf(at, at, 0.1f);
            float cls = (i1.z * i1.z + i1.w * i1.w + i2.x * i2.x
                       + i2.y * i2.y + i2.z * i2.z + i2.w * i2.w) * (1e-8f / 6.0f);
            if (tv.y >= 0) {
                hit_obj(2 * m + 1, rep, tv.y, b, te.y, pe.y, tt_.y, pt_.y,
                        make_float2(tp.z, tp.w), make_float2(pp.z, pp.w), cls);
            } else { nb += b; ncnt += 1.0f; }
        }
    }
    __shared__ float sr[3][8];
    float w0 = warpSum(nb), w1 = warpSum(ncnt), w2 = warpSum(ccs);
    int lane = threadIdx.x & 31, wid = threadIdx.x >> 5;
    if (lane == 0) { sr[0][wid] = w0; sr[1][wid] = w1; sr[2][wid] = w2; }
    __syncthreads();
    if (wid == 0) {
        float v0 = (lane < 8) ? sr[0][lane] : 0.0f;
        float v1 = (lane < 8) ? sr[1][lane] : 0.0f;
        float v2 = (lane < 8) ? sr[2][lane] : 0.0f;
        v0 = warpSum(v0); v1 = warpSum(v1); v2 = warpSum(v2);
        if (lane == 0) {
            if (v1 != 0.0f || v0 != 0.0f) {
                atomicAdd(&g_scal[0], v0);
                atomicAdd(&g_scal[1], v1);
            }
            atomicAdd(&g_scal[2], v2);
        }
    }

    // ---- fused phase 2: last block reduces replicas & builds object data ----
    __shared__ bool lastB;
    if (threadIdx.x == 0) {
        __threadfence();
        unsigned tk = atomicAdd(&g_ticket1, 1u);
        lastB = (tk == (unsigned)(NBX1 - 1));
        if (lastB) g_ticket1 = 0;
    }
    __syncthreads();
    if (!lastB) return;
    __threadfence();

    int t = threadIdx.x;           // 0..255, objects 2t, 2t+1
    int k0 = 2 * t;
    int c0 = 0, c1 = 0;
    float n0 = 0.0f, n1 = 0.0f, d0 = 0.0f, d1 = 0.0f;
    unsigned long long p0 = 0ull, p1 = 0ull;
    #pragma unroll
    for (int r = 0; r < NREP; r++) {
        int2 cvv = *(const int2*)&g_cnt[r][k0];
        float2 nv = *(const float2*)&g_num[r][k0];
        float2 dv = *(const float2*)&g_den[r][k0];
        ulonglong2 pv = *(const ulonglong2*)&g_packed[r][k0];
        c0 += cvv.x; c1 += cvv.y;
        n0 += nv.x; n1 += nv.y;
        d0 += dv.x; d1 += dv.y;
        p0 = (pv.x > p0) ? pv.x : p0;
        p1 = (pv.y > p1) ? pv.y : p1;
    }
    float part = 0.0f, nob = 0.0f, wsum = 0.0f;
    float4 O0 = make_float4(0.0f, 0.0f, 1e6f, 0.0f);
    float4 O1 = make_float4(0.0f, 0.0f, 1e6f, 0.0f);
    float aw0 = 0.0f, aw1 = 0.0f;
    if (c0 > 0) {
        float betaA = __uint_as_float((unsigned)(p0 >> 32));
        unsigned alpha = 0xFFFFFFFFu - (unsigned)(p0 & 0xFFFFFFFFull);
        float2 c = cc[alpha];
        float at = fast_atanh(betaA);
        float qa = fmaf(at, at, 0.1f);
        O0.x = -2.0f * c.x;  O0.y = -2.0f * c.y;
        O0.z = fmaf(c.x, c.x, c.y * c.y) + 1e-6f;
        O0.w = qa / ((float)NHITS - (float)c0 + EPSF);
        aw0 = qa / ((float)c0 + EPSF);
        part += (1.0f - betaA) + n0 / (d0 + EPSF);
        nob += 1.0f; wsum += O0.w;
    }
    if (c1 > 0) {
        float betaA = __uint_as_float((unsigned)(p1 >> 32));
        unsigned alpha = 0xFFFFFFFFu - (unsigned)(p1 & 0xFFFFFFFFull);
        float2 c = cc[alpha];
        float at = fast_atanh(betaA);
        float qa = fmaf(at, at, 0.1f);
        O1.x = -2.0f * c.x;  O1.y = -2.0f * c.y;
        O1.z = fmaf(c.x, c.x, c.y * c.y) + 1e-6f;
        O1.w = qa / ((float)NHITS - (float)c1 + EPSF);
        aw1 = qa / ((float)c1 + EPSF);
        part += (1.0f - betaA) + n1 / (d1 + EPSF);
        nob += 1.0f; wsum += O1.w;
    }
    g_obj[k0]     = O0;
    g_obj[k0 + 1] = O1;
    g_attw[k0] = aw0;
    g_attw[k0 + 1] = aw1;
    // objects 2t,2t+1 -> chunk (2t)>>6 = t>>5 (warp-uniform)
    float ws = warpSum(wsum);
    float wp = warpSum(part);
    float wn = warpSum(nob);
    if ((threadIdx.x & 31) == 0) {
        atomicAdd(&g_wsum[threadIdx.x >> 5], ws);
        atomicAdd(&g_scal[4], wp);
        atomicAdd(&g_scal[6], wn);
    }
}

// ---------------- phase 3: 2 hits/thread, scalar, fully-unrolled K loop ----
__global__ void __launch_bounds__(256) k_phase3(
    const float4* __restrict__ cc4, const int2* __restrict__ tIdx2,
    float* __restrict__ out)
{
    __shared__ float4 sobj[KCHUNK];
    const int kbase = blockIdx.y * KCHUNK;

    int m = blockIdx.x * blockDim.x + threadIdx.x;   // hits 2m, 2m+1
    bool active = (2 * m < NHITS);
    int mc = active ? m : 0;
    float4 cv = cc4[mc];                    // (x0,y0,x1,y1)
    int2   tv = tIdx2[mc];
    float2 qv = *(const float2*)&g_q[2 * mc];

    if (threadIdx.x < KCHUNK) sobj[threadIdx.x] = g_obj[kbase + threadIdx.x];
    // distributed re-zero of the replicated scratch
    {
        int lin = blockIdx.y * NBX3 + blockIdx.x;
        if (threadIdx.x < ZERO_PER_BLOCK) {
            int idx = lin * ZERO_PER_BLOCK + threadIdx.x;
            if (idx < SCRATCH_TOT) {
                ((int*)g_cnt)[idx] = 0;
                ((float*)g_num)[idx] = 0.0f;
                ((float*)g_den)[idx] = 0.0f;
                ((unsigned long long*)g_packed)[idx] = 0ull;
            }
        }
    }
    __syncthreads();

    float res = 0.0f;
    if (active) {
        float x0 = cv.x, y0 = cv.y, x1 = cv.z, y1 = cv.w;
        float h0 = fmaf(x0, x0, y0 * y0);
        float h1 = fmaf(x1, x1, y1 * y1);
        float a00 = 0.0f, a01 = 0.0f, a10 = 0.0f, a11 = 0.0f;
        #pragma unroll
        for (int k = 0; k < KCHUNK; k += 2) {
            {
                float4 o = sobj[k];
                float t0 = fmaf(o.x, x0, o.z); t0 = fmaf(o.y, y0, t0);
                float t1 = fmaf(o.x, x1, o.z); t1 = fmaf(o.y, y1, t1);
                float d20 = fminf(h0 + t0, 1.0f);
                float d21 = fminf(h1 + t1, 1.0f);
                a00 = fmaf(o.w, sqrt_approx(d20), a00);
                a10 = fmaf(o.w, sqrt_approx(d21), a10);
            }
            {
                float4 o = sobj[k + 1];
                float t0 = fmaf(o.x, x0, o.z); t0 = fmaf(o.y, y0, t0);
                float t1 = fmaf(o.x, x1, o.z); t1 = fmaf(o.y, y1, t1);
                float d20 = fminf(h0 + t0, 1.0f);
                float d21 = fminf(h1 + t1, 1.0f);
                a01 = fmaf(o.w, sqrt_approx(d20), a01);
                a11 = fmaf(o.w, sqrt_approx(d21), a11);
            }
        }
        float W = g_wsum[blockIdx.y];
        res = (W - (a00 + a01)) * qv.x + (W - (a10 + a11)) * qv.y;
        // own-object corrections
        #pragma unroll
        for (int i = 0; i < 2; i++) {
            int t = (i == 0) ? tv.x : tv.y;
            if (t >= kbase && t < kbase + KCHUNK) {
                float x = (i == 0) ? x0 : x1;
                float y = (i == 0) ? y0 : y1;
                float qq = (i == 0) ? qv.x : qv.y;
                float4 o = sobj[t - kbase];
                float dx = fmaf(0.5f, o.x, x);
                float dy = fmaf(0.5f, o.y, y);
                float d2n = fmaf(dx, dx, dy * dy);
                float d = sqrt_approx(d2n + 1e-6f);
                res -= fmaxf(1.0f - d, 0.0f) * o.w * qq;
                res = fmaf(d2n * g_attw[t], qq, res);
            }
        }
    }
    __shared__ float sr[8];
    float wv = warpSum(res);
    int lane = threadIdx.x & 31, wid = threadIdx.x >> 5;
    if (lane == 0) sr[wid] = wv;
    __syncthreads();
    __shared__ bool isLast;
    if (threadIdx.x == 0) isLast = false;
    if (wid == 0) {
        float v = (lane < 8) ? sr[lane] : 0.0f;
        v = warpSum(v);
        if (lane == 0) {
            atomicAdd(&g_scal[3], v);
            __threadfence();
            unsigned tk = atomicAdd(&g_ticket3, 1u);
            isLast = (tk == (unsigned)(TOTAL_P3_BLOCKS - 1));
        }
    }
    __syncthreads();
    if (isLast) {
        if (threadIdx.x == 0) {
            float inv = 1.0f / (g_scal[6] + EPSF);
            float total = (g_scal[3] + g_scal[4]) * inv
                        + g_scal[0] / (g_scal[1] + EPSF)
                        + 0.001f * g_scal[2] * (1.0f / ((float)NHITS * 2.0f));
            out[0] = total;
            g_ticket3 = 0;
        }
        __syncthreads();
        if (threadIdx.x < 8) {
            g_scal[threadIdx.x] = 0.0f;
            g_wsum[threadIdx.x] = 0.0f;
        }
    }
}

// ---------------- launch ----------------
extern "C" void kernel_launch(void* const* d_in, const int* in_sizes, int n_in,
                              void* d_out, int out_size)
{
    const float2* pb2   = (const float2*)d_in[0];
    const float4* cc4   = (const float4*)d_in[1];
    const float2* cc2   = (const float2*)d_in[1];
    const float2* pE2   = (const float2*)d_in[2];
    const float4* pPos4 = (const float4*)d_in[3];
    const float2* pT2   = (const float2*)d_in[4];
    const float4* pId4  = (const float4*)d_in[5];
    const int2*   tIdx2 = (const int2*)  d_in[6];
    const float2* tE2   = (const float2*)d_in[7];
    const float4* tPos4 = (const float4*)d_in[8];
    const float2* tT2   = (const float2*)d_in[9];
    float* out = (float*)d_out;

    k_phase1<<<NBX1, 256>>>(pb2, cc4, pE2, pPos4, pT2, pId4, tIdx2, tE2, tPos4, tT2, cc2);
    dim3 g3(NBX3, NCHUNK);
    k_phase3<<<g3, 256>>>(cc4, tIdx2, out);
}